// round 12
// baseline (speedup 1.0000x reference)
#include <cuda_runtime.h>
#include <math.h>

// -------------------------------------------------------------------------
// PrimalLinear: out = x @ quantize(W, scale)^T
// quantize = nearest-neighbor into 16-entry LUT (first-min tie-break), * scale
//
// Math: zeroness of q(ws) depends only on |ws| and its zero-set is an
// interval [0,tau] (LUT sign-symmetric; win condition monotone in ws).
// Division by s is monotone in |w|, so
//     exists i: q(w_i/s) != 0   <=>   q( max_i|w_i| / |s| ) != 0.
//
// Single-stream PDL chain (graph-capturable, no extra streams/events):
//   k1 fill : launch_dependents at entry, then zero-fill out (.cs stores).
//   k2 scan : PDL secondary of k1 -> co-schedules with the fill; no wait
//             before its work (no data dep). launch_dependents at entry for
//             k3. griddepcontrol.wait at the TAIL so scan-complete implies
//             fill-complete (protects the fallback GEMM from racing fill).
//   k3 gemm : PDL secondary of k2: waits, int4-OR-reduces per-block flags,
//             exits when all-zero (expected), else full GEMM overwrite.
// -------------------------------------------------------------------------

#define MAX_SCAN_BLOCKS 2048
__device__ __align__(16) int g_block_nz[MAX_SCAN_BLOCKS]; // overwritten per call

// Exact replica of the reference quantize loop (first strict-min wins).
__device__ __forceinline__ float primal_q(float ws) {
    const float L[16] = { 0.0f, 1.0f, -1.0f, 0.5f, -0.5f,
                          0.333333f, -0.333333f, 0.2f, -0.2f,
                          0.142857f, -0.142857f, 0.090909f, -0.090909f,
                          0.076923f, -0.076923f, 0.0f };
    float best = INFINITY;
    float q = 0.0f;
    #pragma unroll
    for (int i = 0; i < 16; i++) {
        float d = fabsf(ws - L[i]);
        if (d < best) { best = d; q = L[i]; }
    }
    return q;
}

__device__ __forceinline__ float max4abs(float4 v) {
    return fmaxf(fmaxf(fabsf(v.x), fabsf(v.y)), fmaxf(fabsf(v.z), fabsf(v.w)));
}

// Streaming (evict-first) 16B load/store.
__device__ __forceinline__ float4 ldcs4(const float4* p) {
    float4 v;
    asm volatile("ld.global.cs.v4.f32 {%0,%1,%2,%3}, [%4];"
                 : "=f"(v.x), "=f"(v.y), "=f"(v.z), "=f"(v.w) : "l"(p));
    return v;
}
__device__ __forceinline__ void stcs4(float4* p, float4 v) {
    asm volatile("st.global.cs.v4.f32 [%0], {%1,%2,%3,%4};"
                 :: "l"(p), "f"(v.x), "f"(v.y), "f"(v.z), "f"(v.w)
                 : "memory");
}

// ---- k1: zero-fill of out. Releases its PDL dependents immediately. ----
__global__ __launch_bounds__(256)
void fill_kernel(float* __restrict__ out, int nout) {
    asm volatile("griddepcontrol.launch_dependents;");

    const int tid    = blockIdx.x * blockDim.x + threadIdx.x;
    const int stride = gridDim.x * blockDim.x;

    const int no4 = nout >> 2;
    float4* __restrict__ o4 = (float4*)out;
    const float4 z4 = make_float4(0.f, 0.f, 0.f, 0.f);
    int k = tid;
    for (; k + 3 * stride < no4; k += 4 * stride) {
        stcs4(&o4[k],              z4);
        stcs4(&o4[k + stride],     z4);
        stcs4(&o4[k + 2 * stride], z4);
        stcs4(&o4[k + 3 * stride], z4);
    }
    for (; k < no4; k += stride)
        stcs4(&o4[k], z4);
    for (int j = (no4 << 2) + tid; j < nout; j += stride)
        out[j] = 0.0f;
}

// ---- k2: read-only branch-free max-scan. Co-schedules with the fill. ----
__global__ __launch_bounds__(256)
void scan_kernel(const float* __restrict__ w, int nw,
                 const float* __restrict__ scale_p) {
    // Release k3 (gemm) immediately; it blocks on our completion anyway.
    asm volatile("griddepcontrol.launch_dependents;");

    const int tid    = blockIdx.x * blockDim.x + threadIdx.x;
    const int stride = gridDim.x * blockDim.x;

    float m0 = 0.f, m1 = 0.f, m2 = 0.f, m3 = 0.f;
    float m4 = 0.f, m5 = 0.f, m6 = 0.f, m7 = 0.f;
    const int nw4 = nw >> 2;
    const float4* __restrict__ w4 = (const float4*)w;

    int i = tid;
    for (; i + 7 * stride < nw4; i += 8 * stride) {
        float4 a = ldcs4(&w4[i]);
        float4 b = ldcs4(&w4[i + stride]);
        float4 c = ldcs4(&w4[i + 2 * stride]);
        float4 d = ldcs4(&w4[i + 3 * stride]);
        float4 e = ldcs4(&w4[i + 4 * stride]);
        float4 f = ldcs4(&w4[i + 5 * stride]);
        float4 g = ldcs4(&w4[i + 6 * stride]);
        float4 h = ldcs4(&w4[i + 7 * stride]);
        m0 = fmaxf(m0, max4abs(a));
        m1 = fmaxf(m1, max4abs(b));
        m2 = fmaxf(m2, max4abs(c));
        m3 = fmaxf(m3, max4abs(d));
        m4 = fmaxf(m4, max4abs(e));
        m5 = fmaxf(m5, max4abs(f));
        m6 = fmaxf(m6, max4abs(g));
        m7 = fmaxf(m7, max4abs(h));
    }
    for (; i < nw4; i += stride)
        m0 = fmaxf(m0, max4abs(ldcs4(&w4[i])));
    for (int j = (nw4 << 2) + tid; j < nw; j += stride)
        m0 = fmaxf(m0, fabsf(w[j]));

    float mx = fmaxf(fmaxf(fmaxf(m0, m1), fmaxf(m2, m3)),
                     fmaxf(fmaxf(m4, m5), fmaxf(m6, m7)));

    // Tail wait: our grid's completion now implies the fill completed, so
    // k3's wait-on-us transitively orders the fill before any GEMM stores.
    // Costs ~0: the fill finishes long before the scan does.
    asm volatile("griddepcontrol.wait;");

    float ws_max = fabsf(mx / (*scale_p));
    int pred = (primal_q(ws_max) != 0.0f) ? 1 : 0;
    int bnz = __syncthreads_or(pred);
    if (threadIdx.x == 0)
        g_block_nz[blockIdx.x] = bnz;
}

// -------------------------------------------------------------------------
// k3: GEMM fallback. Persistent blocks over 128x128 tiles.
// -------------------------------------------------------------------------
#define GBM 128
#define GBN 128
#define GBK 8
#define GTHREADS 256

__global__ __launch_bounds__(GTHREADS)
void gemm_kernel(const float* __restrict__ x, const float* __restrict__ w,
                 const float* __restrict__ scale_p, float* __restrict__ out,
                 int M, int N, int K, int scan_blocks) {
    asm volatile("griddepcontrol.wait;");

    int nz = 0;
    const int nq = scan_blocks >> 2;
    const int4* f4 = (const int4*)g_block_nz;
    for (int i = threadIdx.x; i < nq; i += GTHREADS) {
        int4 v = f4[i];
        nz |= v.x | v.y | v.z | v.w;
    }
    for (int i = (nq << 2) + threadIdx.x; i < scan_blocks; i += GTHREADS)
        nz |= g_block_nz[i];
    if (!__syncthreads_or(nz)) return;   // expected path: immediate exit

    __shared__ float As[GBK][GBM];
    __shared__ float Bs[GBK][GBN];

    const int ntx = (N + GBN - 1) / GBN;
    const int nty = (M + GBM - 1) / GBM;
    const int numTiles = ntx * nty;

    const int t  = threadIdx.x;
    const int tx = t & 15;
    const int ty = t >> 4;
    const float s = *scale_p;

    for (int tile = blockIdx.x; tile < numTiles; tile += gridDim.x) {
        const int row0 = (tile / ntx) * GBM;
        const int col0 = (tile % ntx) * GBN;

        float acc[8][8];
        #pragma unroll
        for (int i = 0; i < 8; i++)
            #pragma unroll
            for (int j = 0; j < 8; j++) acc[i][j] = 0.0f;

        for (int k0 = 0; k0 < K; k0 += GBK) {
            {
                int r  = t >> 1;
                int kc = (t & 1) * 4;
                int gr = row0 + r;
                #pragma unroll
                for (int j = 0; j < 4; j++) {
                    int gk = k0 + kc + j;
                    As[kc + j][r] = (gr < M && gk < K)
                        ? x[(long long)gr * K + gk] : 0.0f;
                }
            }
            {
                int r  = t >> 1;
                int kc = (t & 1) * 4;
                int gn = col0 + r;
                #pragma unroll
                for (int j = 0; j < 4; j++) {
                    int gk = k0 + kc + j;
                    float wv = (gn < N && gk < K)
                        ? w[(long long)gn * K + gk] : 0.0f;
                    Bs[kc + j][r] = primal_q(wv / s) * s;
                }
            }
            __syncthreads();

            #pragma unroll
            for (int k = 0; k < GBK; k++) {
                float a[8], b[8];
                #pragma unroll
                for (int i = 0; i < 8; i++) a[i] = As[k][ty * 8 + i];
                #pragma unroll
                for (int j = 0; j < 8; j++) b[j] = Bs[k][tx * 8 + j];
                #pragma unroll
                for (int i = 0; i < 8; i++)
                    #pragma unroll
                    for (int j = 0; j < 8; j++)
                        acc[i][j] = fmaf(a[i], b[j], acc[i][j]);
            }
            __syncthreads();
        }

        #pragma unroll
        for (int i = 0; i < 8; i++) {
            int row = row0 + ty * 8 + i;
            if (row >= M) continue;
            #pragma unroll
            for (int j = 0; j < 8; j++) {
                int col = col0 + tx * 8 + j;
                if (col < N) out[(long long)row * N + col] = acc[i][j];
            }
        }
        __syncthreads();
    }
}

extern "C" void kernel_launch(void* const* d_in, const int* in_sizes, int n_in,
                              void* d_out, int out_size) {
    const float* x     = (const float*)d_in[0];
    const float* w     = (const float*)d_in[1];
    const float* scale = (const float*)d_in[2];
    float*       out   = (float*)d_out;

    const long long Sx = in_sizes[0];   // M*K
    const long long Sw = in_sizes[1];   // N*K
    const long long So = out_size;      // M*N

    long long K = (long long)(sqrt((double)Sx * (double)Sw / (double)So) + 0.5);
    long long M = Sx / K;
    long long N = Sw / K;

    // One-time cached host queries (no allocations, no streams/events).
    static int sms = 0;
    static int scan_occ = 0;
    if (sms == 0) {
        int dev = 0;
        cudaGetDevice(&dev);
        if (cudaDeviceGetAttribute(&sms, cudaDevAttrMultiProcessorCount, dev)
                != cudaSuccess || sms <= 0)
            sms = 148;
        if (cudaOccupancyMaxActiveBlocksPerMultiprocessor(
                &scan_occ, scan_kernel, 256, 0) != cudaSuccess ||
            scan_occ <= 0)
            scan_occ = 4;
    }

    int scan_blocks = sms * scan_occ;
    if (scan_blocks > MAX_SCAN_BLOCKS) scan_blocks = MAX_SCAN_BLOCKS;
    if (scan_blocks < 1) scan_blocks = 1;

    int ntx = (int)((N + GBN - 1) / GBN);
    int nty = (int)((M + GBM - 1) / GBM);
    long long tiles = (long long)ntx * nty;
    int gemm_blocks = (int)(tiles < (long long)sms ? tiles : (long long)sms);
    if (gemm_blocks < 1) gemm_blocks = 1;

    // PDL launch config (shared attr setup).
    cudaLaunchAttribute attr[1];
    attr[0].id = cudaLaunchAttributeProgrammaticStreamSerialization;
    attr[0].val.programmaticStreamSerializationAllowed = 1;

    // k1: fill (primary of the chain; plain launch).
    fill_kernel<<<sms, 256>>>(out, (int)So);

    // k2: scan, PDL-launched -> co-schedules with the fill.
    {
        cudaLaunchConfig_t cfg = {};
        cfg.gridDim  = dim3((unsigned)scan_blocks, 1, 1);
        cfg.blockDim = dim3(256, 1, 1);
        cfg.dynamicSmemBytes = 0;
        cfg.stream = 0;
        cfg.attrs = attr;
        cfg.numAttrs = 1;
        cudaError_t e = cudaLaunchKernelEx(&cfg, scan_kernel,
                                           w, (int)Sw, scale);
        if (e != cudaSuccess) {
            // Serialized fallback (still correct: fill precedes scan).
            scan_kernel<<<scan_blocks, 256>>>(w, (int)Sw, scale);
        }
    }

    // k3: gemm, PDL-launched (waits on scan; transitively on fill).
    {
        cudaLaunchConfig_t cfg = {};
        cfg.gridDim  = dim3((unsigned)gemm_blocks, 1, 1);
        cfg.blockDim = dim3(GTHREADS, 1, 1);
        cfg.dynamicSmemBytes = 0;
        cfg.stream = 0;
        cfg.attrs = attr;
        cfg.numAttrs = 1;
        cudaError_t e = cudaLaunchKernelEx(&cfg, gemm_kernel,
                                           x, w, scale, out,
                                           (int)M, (int)N, (int)K,
                                           scan_blocks);
        if (e != cudaSuccess) {
            gemm_kernel<<<gemm_blocks, GTHREADS>>>(x, w, scale, out,
                                                   (int)M, (int)N, (int)K,
                                                   scan_blocks);
        }
    }
}

// round 14
// speedup vs baseline: 1.0569x; 1.0569x over previous
#include <cuda_runtime.h>
#include <cstdint>
#include <math.h>

// -------------------------------------------------------------------------
// PrimalLinear: out = x @ quantize(W, scale)^T
// quantize = nearest-neighbor into 16-entry LUT (first-min tie-break), * scale
//
// Math: zeroness of q(ws) depends only on |ws|; its zero-set is an interval
// [0,tau] (LUT sign-symmetric; win condition monotone). Division by s is
// monotone in |w|, so
//     exists i: q(w_i/s) != 0   <=>   q( max_i|w_i| / |s| ) != 0.
//
// Key change (R13/R14): the 33.5 MB zero-fill is issued as TMA bulk stores
// (cp.async.bulk smem->gmem, ~2048 descriptors) instead of ~2.1M STG.128 —
// the fill leaves the warps' LSU issue slots entirely and drains on the TMA
// engine WHILE the LDG max-scan runs. wait_group 0 after the scan (free).
//
// Pipeline (graph-capturable, single stream):
//   k1 : TMA-fill(out)=0 + branch-free max-scan(W); per-block flag publish.
//        PDL primary.
//   k2 : GEMM fallback, PDL secondary: waits, int4-OR-reduces flags,
//        exits when all-zero (expected path).
// -------------------------------------------------------------------------

#define MAX_SCAN_BLOCKS 2048
#define FILL_CHUNK 16384              // 16 KB per bulk store
__device__ __align__(16) int g_block_nz[MAX_SCAN_BLOCKS]; // overwritten per call

// Exact replica of the reference quantize loop (first strict-min wins).
__device__ __forceinline__ float primal_q(float ws) {
    const float L[16] = { 0.0f, 1.0f, -1.0f, 0.5f, -0.5f,
                          0.333333f, -0.333333f, 0.2f, -0.2f,
                          0.142857f, -0.142857f, 0.090909f, -0.090909f,
                          0.076923f, -0.076923f, 0.0f };
    float best = INFINITY;
    float q = 0.0f;
    #pragma unroll
    for (int i = 0; i < 16; i++) {
        float d = fabsf(ws - L[i]);
        if (d < best) { best = d; q = L[i]; }
    }
    return q;
}

__device__ __forceinline__ float max4abs(float4 v) {
    return fmaxf(fmaxf(fabsf(v.x), fabsf(v.y)), fmaxf(fabsf(v.z), fabsf(v.w)));
}

// Streaming (evict-first) 16B load — weight stream.
__device__ __forceinline__ float4 ldcs4(const float4* p) {
    float4 v;
    asm volatile("ld.global.cs.v4.f32 {%0,%1,%2,%3}, [%4];"
                 : "=f"(v.x), "=f"(v.y), "=f"(v.z), "=f"(v.w) : "l"(p));
    return v;
}

// Fused: TMA bulk-store zero-fill + branch-free max-scan of W.
__global__ __launch_bounds__(256)
void scan_fill_kernel(const float* __restrict__ w, int nw,
                      const float* __restrict__ scale_p,
                      float* __restrict__ out, int nout) {
    // Release the dependent (GEMM) kernel's launch immediately.
    asm volatile("griddepcontrol.launch_dependents;");

    __shared__ __align__(128) float s_zero[FILL_CHUNK / 4];   // 16 KB of zeros

    const int tid    = blockIdx.x * blockDim.x + threadIdx.x;
    const int stride = gridDim.x * blockDim.x;

    // ---- zero the smem staging buffer (4 x 16B per thread) ----
    {
        float4* sz = (float4*)s_zero;
        const float4 z4 = make_float4(0.f, 0.f, 0.f, 0.f);
        #pragma unroll
        for (int r = 0; r < (FILL_CHUNK / 16) / 256; r++)
            sz[threadIdx.x + r * 256] = z4;
    }
    __syncthreads();
    asm volatile("fence.proxy.async.shared::cta;" ::: "memory");

    // ---- issue TMA bulk stores: out[...] = smem zeros, 16 KB per op ----
    // TMA engine drains these WHILE the scan below runs on the warps.
    const long long total_bytes = (long long)nout * 4;
    const int full_chunks = (int)(total_bytes / FILL_CHUNK);
    bool issued = false;
    if (threadIdx.x == 0) {
        unsigned int saddr;
        asm("{ .reg .u64 t; cvta.to.shared.u64 t, %1; cvt.u32.u64 %0, t; }"
            : "=r"(saddr) : "l"(s_zero));
        char* ob = (char*)out;
        for (int c = blockIdx.x; c < full_chunks; c += gridDim.x) {
            asm volatile(
                "cp.async.bulk.global.shared::cta.bulk_group [%0], [%1], %2;"
                :: "l"(ob + (long long)c * FILL_CHUNK), "r"(saddr),
                   "r"((unsigned int)FILL_CHUNK)
                : "memory");
            issued = true;
        }
        if (issued)
            asm volatile("cp.async.bulk.commit_group;" ::: "memory");
    }
    // Tail (bytes beyond the last full 16KB chunk): scalar stores.
    {
        const long long tail_start = (long long)full_chunks * (FILL_CHUNK / 4);
        for (long long j = tail_start + tid; j < nout; j += stride)
            out[j] = 0.0f;
    }

    // ---- branch-free max|w| scan, unroll x8 (independent accumulators) ----
    float m0 = 0.f, m1 = 0.f, m2 = 0.f, m3 = 0.f;
    float m4 = 0.f, m5 = 0.f, m6 = 0.f, m7 = 0.f;
    const int nw4 = nw >> 2;
    const float4* __restrict__ w4 = (const float4*)w;

    int i = tid;
    for (; i + 7 * stride < nw4; i += 8 * stride) {
        float4 a = ldcs4(&w4[i]);
        float4 b = ldcs4(&w4[i + stride]);
        float4 c = ldcs4(&w4[i + 2 * stride]);
        float4 d = ldcs4(&w4[i + 3 * stride]);
        float4 e = ldcs4(&w4[i + 4 * stride]);
        float4 f = ldcs4(&w4[i + 5 * stride]);
        float4 g = ldcs4(&w4[i + 6 * stride]);
        float4 h = ldcs4(&w4[i + 7 * stride]);
        m0 = fmaxf(m0, max4abs(a));
        m1 = fmaxf(m1, max4abs(b));
        m2 = fmaxf(m2, max4abs(c));
        m3 = fmaxf(m3, max4abs(d));
        m4 = fmaxf(m4, max4abs(e));
        m5 = fmaxf(m5, max4abs(f));
        m6 = fmaxf(m6, max4abs(g));
        m7 = fmaxf(m7, max4abs(h));
    }
    for (; i < nw4; i += stride)
        m0 = fmaxf(m0, max4abs(ldcs4(&w4[i])));
    for (int j = (nw4 << 2) + tid; j < nw; j += stride)
        m0 = fmaxf(m0, fabsf(w[j]));

    float mx = fmaxf(fmaxf(fmaxf(m0, m1), fmaxf(m2, m3)),
                     fmaxf(fmaxf(m4, m5), fmaxf(m6, m7)));

    // ---- exact predicate on per-thread max, block-OR ----
    float ws_max = fabsf(mx / (*scale_p));
    int pred = (primal_q(ws_max) != 0.0f) ? 1 : 0;
    int bnz = __syncthreads_or(pred);

    if (threadIdx.x == 0) {
        // Ensure all this block's bulk fill stores committed before grid
        // completion (the scan gave the TMA engine ~20us of runway: free).
        if (issued)
            asm volatile("cp.async.bulk.wait_group 0;" ::: "memory");
        g_block_nz[blockIdx.x] = bnz;
    }
}

// -------------------------------------------------------------------------
// GEMM fallback: persistent blocks, grid-stride over 128x128 output tiles.
// PDL secondary: waits on scan grid, int4-OR-reduces the per-block flags.
// -------------------------------------------------------------------------
#define GBM 128
#define GBN 128
#define GBK 8
#define GTHREADS 256

__global__ __launch_bounds__(GTHREADS)
void gemm_kernel(const float* __restrict__ x, const float* __restrict__ w,
                 const float* __restrict__ scale_p, float* __restrict__ out,
                 int M, int N, int K, int scan_blocks) {
    asm volatile("griddepcontrol.wait;");

    int nz = 0;
    const int nq = scan_blocks >> 2;
    const int4* f4 = (const int4*)g_block_nz;
    for (int i = threadIdx.x; i < nq; i += GTHREADS) {
        int4 v = f4[i];
        nz |= v.x | v.y | v.z | v.w;
    }
    for (int i = (nq << 2) + threadIdx.x; i < scan_blocks; i += GTHREADS)
        nz |= g_block_nz[i];
    if (!__syncthreads_or(nz)) return;   // expected path: immediate exit

    __shared__ float As[GBK][GBM];
    __shared__ float Bs[GBK][GBN];

    const int ntx = (N + GBN - 1) / GBN;
    const int nty = (M + GBM - 1) / GBM;
    const int numTiles = ntx * nty;

    const int t  = threadIdx.x;
    const int tx = t & 15;
    const int ty = t >> 4;
    const float s = *scale_p;

    for (int tile = blockIdx.x; tile < numTiles; tile += gridDim.x) {
        const int row0 = (tile / ntx) * GBM;
        const int col0 = (tile % ntx) * GBN;

        float acc[8][8];
        #pragma unroll
        for (int i = 0; i < 8; i++)
            #pragma unroll
            for (int j = 0; j < 8; j++) acc[i][j] = 0.0f;

        for (int k0 = 0; k0 < K; k0 += GBK) {
            {
                int r  = t >> 1;
                int kc = (t & 1) * 4;
                int gr = row0 + r;
                #pragma unroll
                for (int j = 0; j < 4; j++) {
                    int gk = k0 + kc + j;
                    As[kc + j][r] = (gr < M && gk < K)
                        ? x[(long long)gr * K + gk] : 0.0f;
                }
            }
            {
                int r  = t >> 1;
                int kc = (t & 1) * 4;
                int gn = col0 + r;
                #pragma unroll
                for (int j = 0; j < 4; j++) {
                    int gk = k0 + kc + j;
                    float wv = (gn < N && gk < K)
                        ? w[(long long)gn * K + gk] : 0.0f;
                    Bs[kc + j][r] = primal_q(wv / s) * s;
                }
            }
            __syncthreads();

            #pragma unroll
            for (int k = 0; k < GBK; k++) {
                float a[8], b[8];
                #pragma unroll
                for (int i = 0; i < 8; i++) a[i] = As[k][ty * 8 + i];
                #pragma unroll
                for (int j = 0; j < 8; j++) b[j] = Bs[k][tx * 8 + j];
                #pragma unroll
                for (int i = 0; i < 8; i++)
                    #pragma unroll
                    for (int j = 0; j < 8; j++)
                        acc[i][j] = fmaf(a[i], b[j], acc[i][j]);
            }
            __syncthreads();
        }

        #pragma unroll
        for (int i = 0; i < 8; i++) {
            int row = row0 + ty * 8 + i;
            if (row >= M) continue;
            #pragma unroll
            for (int j = 0; j < 8; j++) {
                int col = col0 + tx * 8 + j;
                if (col < N) out[(long long)row * N + col] = acc[i][j];
            }
        }
        __syncthreads();
    }
}

extern "C" void kernel_launch(void* const* d_in, const int* in_sizes, int n_in,
                              void* d_out, int out_size) {
    const float* x     = (const float*)d_in[0];
    const float* w     = (const float*)d_in[1];
    const float* scale = (const float*)d_in[2];
    float*       out   = (float*)d_out;

    const long long Sx = in_sizes[0];   // M*K
    const long long Sw = in_sizes[1];   // N*K
    const long long So = out_size;      // M*N

    long long K = (long long)(sqrt((double)Sx * (double)Sw / (double)So) + 0.5);
    long long M = Sx / K;
    long long N = Sw / K;

    static int sms = 0;
    static int scan_occ = 0;
    if (sms == 0) {
        int dev = 0;
        cudaGetDevice(&dev);
        if (cudaDeviceGetAttribute(&sms, cudaDevAttrMultiProcessorCount, dev)
                != cudaSuccess || sms <= 0)
            sms = 148;
        if (cudaOccupancyMaxActiveBlocksPerMultiprocessor(
                &scan_occ, scan_fill_kernel, 256, 0) != cudaSuccess ||
            scan_occ <= 0)
            scan_occ = 4;
    }

    int scan_blocks = sms * scan_occ;
    if (scan_blocks > MAX_SCAN_BLOCKS) scan_blocks = MAX_SCAN_BLOCKS;
    if (scan_blocks < 1) scan_blocks = 1;
    scan_fill_kernel<<<scan_blocks, 256>>>(w, (int)Sw, scale, out, (int)So);

    int ntx = (int)((N + GBN - 1) / GBN);
    int nty = (int)((M + GBM - 1) / GBM);
    long long tiles = (long long)ntx * nty;
    int gemm_blocks = (int)(tiles < (long long)sms ? tiles : (long long)sms);
    if (gemm_blocks < 1) gemm_blocks = 1;

    cudaLaunchConfig_t cfg = {};
    cfg.gridDim  = dim3((unsigned)gemm_blocks, 1, 1);
    cfg.blockDim = dim3(GTHREADS, 1, 1);
    cfg.dynamicSmemBytes = 0;
    cfg.stream = 0;
    cudaLaunchAttribute attr[1];
    attr[0].id = cudaLaunchAttributeProgrammaticStreamSerialization;
    attr[0].val.programmaticStreamSerializationAllowed = 1;
    cfg.attrs = attr;
    cfg.numAttrs = 1;

    cudaError_t e = cudaLaunchKernelEx(&cfg, gemm_kernel,
                                       x, w, scale, out,
                                       (int)M, (int)N, (int)K, scan_blocks);
    if (e != cudaSuccess) {
        gemm_kernel<<<gemm_blocks, GTHREADS>>>(x, w, scale, out,
                                               (int)M, (int)N, (int)K,
                                               scan_blocks);
    }
}

// round 15
// speedup vs baseline: 1.1404x; 1.0789x over previous
#include <cuda_runtime.h>
#include <math.h>

// -------------------------------------------------------------------------
// PrimalLinear: out = x @ quantize(W, scale)^T
// quantize = nearest-neighbor into 16-entry LUT (first-min tie-break), * scale
//
// Math: zeroness of q(ws) depends only on |ws| and its zero-set is an
// interval [0,tau] (LUT sign-symmetric; win condition monotone in ws).
// Division by s is monotone in |w|, so
//     exists i: q(w_i/s) != 0   <=>   q( max_i|w_i| / |s| ) != 0.
// The scan is a branch-free max|w| reduction (pure streaming HBM) with ONE
// exact-reference quantizer evaluation per thread at the end.
//
// Measured model (R10/R12/R14): the fused kernel is DRAM-capped at
// ~5.9 TB/s; 168 MB of irreducible traffic => ~28.5us kernel floor. The
// only tunable remainder is the launch/exit tail, addressed here by a
// smaller gemm exit wave.
//
// Pipeline (graph-capturable, NO memset, NO atomics):
//   k1 : fused zero-fill(out) [.cs stores, first] + max-scan(W) [.cs loads];
//        per-block flags. One occupancy-matched wave. PDL primary.
//   k2 : GEMM fallback (64 persistent blocks), PDL secondary: waits,
//        int4-OR-reduces flags, exits immediately when all-zero.
// -------------------------------------------------------------------------

#define MAX_SCAN_BLOCKS 2048
__device__ __align__(16) int g_block_nz[MAX_SCAN_BLOCKS]; // overwritten per call

// Exact replica of the reference quantize loop (first strict-min wins).
__device__ __forceinline__ float primal_q(float ws) {
    const float L[16] = { 0.0f, 1.0f, -1.0f, 0.5f, -0.5f,
                          0.333333f, -0.333333f, 0.2f, -0.2f,
                          0.142857f, -0.142857f, 0.090909f, -0.090909f,
                          0.076923f, -0.076923f, 0.0f };
    float best = INFINITY;
    float q = 0.0f;
    #pragma unroll
    for (int i = 0; i < 16; i++) {
        float d = fabsf(ws - L[i]);
        if (d < best) { best = d; q = L[i]; }
    }
    return q;
}

__device__ __forceinline__ float max4abs(float4 v) {
    return fmaxf(fmaxf(fabsf(v.x), fabsf(v.y)), fmaxf(fabsf(v.z), fabsf(v.w)));
}

// Streaming (evict-first) 16B load/store.
__device__ __forceinline__ float4 ldcs4(const float4* p) {
    float4 v;
    asm volatile("ld.global.cs.v4.f32 {%0,%1,%2,%3}, [%4];"
                 : "=f"(v.x), "=f"(v.y), "=f"(v.z), "=f"(v.w) : "l"(p));
    return v;
}
__device__ __forceinline__ void stcs4(float4* p, float4 v) {
    asm volatile("st.global.cs.v4.f32 [%0], {%1,%2,%3,%4};"
                 :: "l"(p), "f"(v.x), "f"(v.y), "f"(v.z), "f"(v.w)
                 : "memory");
}

// Fused: zero-fill of out (first) + branch-free max-scan of W. 32-bit idx.
__global__ __launch_bounds__(256)
void scan_fill_kernel(const float* __restrict__ w, int nw,
                      const float* __restrict__ scale_p,
                      float* __restrict__ out, int nout) {
    // Let the dependent (GEMM) kernel's launch overlap this grid.
    asm volatile("griddepcontrol.launch_dependents;");

    const int tid    = blockIdx.x * blockDim.x + threadIdx.x;
    const int stride = gridDim.x * blockDim.x;

    // ---- zero-fill output FIRST (stores drain under the read stream) ----
    const int no4 = nout >> 2;
    float4* __restrict__ o4 = (float4*)out;
    const float4 z4 = make_float4(0.f, 0.f, 0.f, 0.f);
    int k = tid;
    for (; k + 3 * stride < no4; k += 4 * stride) {
        stcs4(&o4[k],              z4);
        stcs4(&o4[k + stride],     z4);
        stcs4(&o4[k + 2 * stride], z4);
        stcs4(&o4[k + 3 * stride], z4);
    }
    for (; k < no4; k += stride)
        stcs4(&o4[k], z4);
    for (int j = (no4 << 2) + tid; j < nout; j += stride)
        out[j] = 0.0f;

    // ---- branch-free max|w| scan, unroll x8 (independent accumulators) ----
    float m0 = 0.f, m1 = 0.f, m2 = 0.f, m3 = 0.f;
    float m4 = 0.f, m5 = 0.f, m6 = 0.f, m7 = 0.f;
    const int nw4 = nw >> 2;
    const float4* __restrict__ w4 = (const float4*)w;

    int i = tid;
    for (; i + 7 * stride < nw4; i += 8 * stride) {
        float4 a = ldcs4(&w4[i]);
        float4 b = ldcs4(&w4[i + stride]);
        float4 c = ldcs4(&w4[i + 2 * stride]);
        float4 d = ldcs4(&w4[i + 3 * stride]);
        float4 e = ldcs4(&w4[i + 4 * stride]);
        float4 f = ldcs4(&w4[i + 5 * stride]);
        float4 g = ldcs4(&w4[i + 6 * stride]);
        float4 h = ldcs4(&w4[i + 7 * stride]);
        m0 = fmaxf(m0, max4abs(a));
        m1 = fmaxf(m1, max4abs(b));
        m2 = fmaxf(m2, max4abs(c));
        m3 = fmaxf(m3, max4abs(d));
        m4 = fmaxf(m4, max4abs(e));
        m5 = fmaxf(m5, max4abs(f));
        m6 = fmaxf(m6, max4abs(g));
        m7 = fmaxf(m7, max4abs(h));
    }
    for (; i < nw4; i += stride)
        m0 = fmaxf(m0, max4abs(ldcs4(&w4[i])));
    for (int j = (nw4 << 2) + tid; j < nw; j += stride)
        m0 = fmaxf(m0, fabsf(w[j]));

    float mx = fmaxf(fmaxf(fmaxf(m0, m1), fmaxf(m2, m3)),
                     fmaxf(fmaxf(m4, m5), fmaxf(m6, m7)));

    // ---- exact predicate on per-thread max, block-OR, plain store ----
    float ws_max = fabsf(mx / (*scale_p));
    int pred = (primal_q(ws_max) != 0.0f) ? 1 : 0;
    int bnz = __syncthreads_or(pred);
    if (threadIdx.x == 0)
        g_block_nz[blockIdx.x] = bnz;
}

// -------------------------------------------------------------------------
// GEMM fallback: persistent blocks, grid-stride over 128x128 output tiles.
// PDL secondary: waits on scan grid, int4-OR-reduces the per-block flags.
// -------------------------------------------------------------------------
#define GBM 128
#define GBN 128
#define GBK 8
#define GTHREADS 256
#define GEMM_MAX_BLOCKS 64

__global__ __launch_bounds__(GTHREADS)
void gemm_kernel(const float* __restrict__ x, const float* __restrict__ w,
                 const float* __restrict__ scale_p, float* __restrict__ out,
                 int M, int N, int K, int scan_blocks) {
    // Block until the scan grid has fully completed (memory visible).
    asm volatile("griddepcontrol.wait;");

    // OR-reduce the per-block predicates with independent int4 loads.
    int nz = 0;
    const int nq = scan_blocks >> 2;
    const int4* f4 = (const int4*)g_block_nz;
    for (int i = threadIdx.x; i < nq; i += GTHREADS) {
        int4 v = f4[i];
        nz |= v.x | v.y | v.z | v.w;
    }
    for (int i = (nq << 2) + threadIdx.x; i < scan_blocks; i += GTHREADS)
        nz |= g_block_nz[i];
    if (!__syncthreads_or(nz)) return;   // expected path: immediate exit

    __shared__ float As[GBK][GBM];
    __shared__ float Bs[GBK][GBN];

    const int ntx = (N + GBN - 1) / GBN;
    const int nty = (M + GBM - 1) / GBM;
    const int numTiles = ntx * nty;

    const int t  = threadIdx.x;
    const int tx = t & 15;
    const int ty = t >> 4;
    const float s = *scale_p;

    for (int tile = blockIdx.x; tile < numTiles; tile += gridDim.x) {
        const int row0 = (tile / ntx) * GBM;
        const int col0 = (tile % ntx) * GBN;

        float acc[8][8];
        #pragma unroll
        for (int i = 0; i < 8; i++)
            #pragma unroll
            for (int j = 0; j < 8; j++) acc[i][j] = 0.0f;

        for (int k0 = 0; k0 < K; k0 += GBK) {
            {
                int r  = t >> 1;
                int kc = (t & 1) * 4;
                int gr = row0 + r;
                #pragma unroll
                for (int j = 0; j < 4; j++) {
                    int gk = k0 + kc + j;
                    As[kc + j][r] = (gr < M && gk < K)
                        ? x[(long long)gr * K + gk] : 0.0f;
                }
            }
            {
                int r  = t >> 1;
                int kc = (t & 1) * 4;
                int gn = col0 + r;
                #pragma unroll
                for (int j = 0; j < 4; j++) {
                    int gk = k0 + kc + j;
                    float wv = (gn < N && gk < K)
                        ? w[(long long)gn * K + gk] : 0.0f;
                    Bs[kc + j][r] = primal_q(wv / s) * s;
                }
            }
            __syncthreads();

            #pragma unroll
            for (int k = 0; k < GBK; k++) {
                float a[8], b[8];
                #pragma unroll
                for (int i = 0; i < 8; i++) a[i] = As[k][ty * 8 + i];
                #pragma unroll
                for (int j = 0; j < 8; j++) b[j] = Bs[k][tx * 8 + j];
                #pragma unroll
                for (int i = 0; i < 8; i++)
                    #pragma unroll
                    for (int j = 0; j < 8; j++)
                        acc[i][j] = fmaf(a[i], b[j], acc[i][j]);
            }
            __syncthreads();
        }

        #pragma unroll
        for (int i = 0; i < 8; i++) {
            int row = row0 + ty * 8 + i;
            if (row >= M) continue;
            #pragma unroll
            for (int j = 0; j < 8; j++) {
                int col = col0 + tx * 8 + j;
                if (col < N) out[(long long)row * N + col] = acc[i][j];
            }
        }
        __syncthreads();
    }
}

extern "C" void kernel_launch(void* const* d_in, const int* in_sizes, int n_in,
                              void* d_out, int out_size) {
    const float* x     = (const float*)d_in[0];
    const float* w     = (const float*)d_in[1];
    const float* scale = (const float*)d_in[2];
    float*       out   = (float*)d_out;

    const long long Sx = in_sizes[0];   // M*K
    const long long Sw = in_sizes[1];   // N*K
    const long long So = out_size;      // M*N

    long long K = (long long)(sqrt((double)Sx * (double)Sw / (double)So) + 0.5);
    long long M = Sx / K;
    long long N = Sw / K;

    // One-time cached host queries (no allocations).
    static int sms = 0;
    static int scan_occ = 0;
    if (sms == 0) {
        int dev = 0;
        cudaGetDevice(&dev);
        if (cudaDeviceGetAttribute(&sms, cudaDevAttrMultiProcessorCount, dev)
                != cudaSuccess || sms <= 0)
            sms = 148;
        if (cudaOccupancyMaxActiveBlocksPerMultiprocessor(
                &scan_occ, scan_fill_kernel, 256, 0) != cudaSuccess ||
            scan_occ <= 0)
            scan_occ = 4;
    }

    // Exactly one resident wave, matched to true occupancy.
    int scan_blocks = sms * scan_occ;
    if (scan_blocks > MAX_SCAN_BLOCKS) scan_blocks = MAX_SCAN_BLOCKS;
    if (scan_blocks < 1) scan_blocks = 1;
    scan_fill_kernel<<<scan_blocks, 256>>>(w, (int)Sw, scale, out, (int)So);

    // GEMM fallback: small persistent exit wave, PDL-launched.
    int ntx = (int)((N + GBN - 1) / GBN);
    int nty = (int)((M + GBM - 1) / GBM);
    long long tiles = (long long)ntx * nty;
    int gemm_blocks = (int)(tiles < (long long)GEMM_MAX_BLOCKS
                                ? tiles : (long long)GEMM_MAX_BLOCKS);
    if (gemm_blocks < 1) gemm_blocks = 1;

    cudaLaunchConfig_t cfg = {};
    cfg.gridDim  = dim3((unsigned)gemm_blocks, 1, 1);
    cfg.blockDim = dim3(GTHREADS, 1, 1);
    cfg.dynamicSmemBytes = 0;
    cfg.stream = 0;
    cudaLaunchAttribute attr[1];
    attr[0].id = cudaLaunchAttributeProgrammaticStreamSerialization;
    attr[0].val.programmaticStreamSerializationAllowed = 1;
    cfg.attrs = attr;
    cfg.numAttrs = 1;

    cudaError_t e = cudaLaunchKernelEx(&cfg, gemm_kernel,
                                       x, w, scale, out,
                                       (int)M, (int)N, (int)K, scan_blocks);
    if (e != cudaSuccess) {
        // Plain launch: stream order still guarantees scan completion.
        gemm_kernel<<<gemm_blocks, GTHREADS>>>(x, w, scale, out,
                                               (int)M, (int)N, (int)K,
                                               scan_blocks);
    }
}